// round 2
// baseline (speedup 1.0000x reference)
#include <cuda_runtime.h>
#include <cuda_bf16.h>
#include <math.h>
#include <stdint.h>

// Shapes: B=2, S=128, H=8, KD=64, D=512, FB=512
#define NB   2
#define NS   128
#define NH   8
#define NKD  64
#define ND   512
#define NFB  512
#define NBHQ 2048          // B*H*S

// ---------------- device scratch (no allocations allowed) ----------------
__device__ float g_eqk[NB*NS*ND];          // elu(q @ Wkq + bkq)
__device__ float g_eqv[NB*NS*ND];          // elu(q @ Wvq + bvq)
__device__ float g_ekk[NB*NS*ND];          // elu(v @ Wk  + bk )
__device__ float g_evv[NB*NS*ND];          // elu(v @ Wv  + bv )
__device__ float g_logit_part[2*NBHQ*NS];  // [fh][bhq][k] partial logits
__device__ float g_pool[NBHQ*NFB];         // [bhq][f] masked pool sums
__device__ float g_O[NB*NS*ND];            // pre-final-projection output

// ---------------- f32x2 helpers (sm_100a packed fp32 pipe) ----------------
__device__ __forceinline__ unsigned long long pack2(float x, float y) {
    unsigned long long r;
    asm("mov.b64 %0, {%1, %2};" : "=l"(r) : "f"(x), "f"(y));
    return r;
}
__device__ __forceinline__ void fma2(unsigned long long& acc, unsigned long long a,
                                     unsigned long long b) {
    asm("fma.rn.f32x2 %0, %1, %2, %0;" : "+l"(acc) : "l"(a), "l"(b));
}
__device__ __forceinline__ unsigned long long add2(unsigned long long a,
                                                   unsigned long long b) {
    unsigned long long r;
    asm("add.rn.f32x2 %0, %1, %2;" : "=l"(r) : "l"(a), "l"(b));
    return r;
}
__device__ __forceinline__ float2 unpack2(unsigned long long v) {
    float2 f;
    asm("mov.b64 {%0, %1}, %2;" : "=f"(f.x), "=f"(f.y) : "l"(v));
    return f;
}
__device__ __forceinline__ float elu_f(float x) {
    return (x > 0.f) ? x : expm1f(x);
}

// =====================================================================
// Kernel 1: the four projections + elu.
//   z=0: eqk = elu(q@Wkq+bkq)   z=1: eqv = elu(q@Wvq+bvq)
//   z=2: ekk = elu(v@Wk +bk )   z=3: evv = elu(v@Wv +bv )
// Tiled 64x64 GEMM, (256x512)@(512x512). grid (8, 4, 4), 256 threads.
// =====================================================================
__global__ __launch_bounds__(256) void k_proj(
    const float* __restrict__ q, const float* __restrict__ v,
    const float* __restrict__ Wkq, const float* __restrict__ bkq,
    const float* __restrict__ Wvq, const float* __restrict__ bvq,
    const float* __restrict__ Wk,  const float* __restrict__ bk,
    const float* __restrict__ Wv,  const float* __restrict__ bv)
{
    int z = blockIdx.z;
    const float* X    = (z < 2) ? q : v;
    const float* W    = (z == 0) ? Wkq : (z == 1) ? Wvq : (z == 2) ? Wk : Wv;
    const float* bias = (z == 0) ? bkq : (z == 1) ? bvq : (z == 2) ? bk : bv;
    float* Y          = (z == 0) ? g_eqk : (z == 1) ? g_eqv : (z == 2) ? g_ekk : g_evv;

    __shared__ float As[16][64];    // A^T tile: As[k][m]
    __shared__ float Bs[16][64];    // B tile:   Bs[k][n]

    int tid = threadIdx.x;
    int tx = tid & 15;          // 0..15 -> col group
    int ty = tid >> 4;          // 0..15 -> row group
    int n0 = blockIdx.x * 64;
    int m0 = blockIdx.y * 64;

    float acc[4][4];
    #pragma unroll
    for (int i = 0; i < 4; i++)
        #pragma unroll
        for (int j = 0; j < 4; j++) acc[i][j] = 0.f;

    int ar = tid >> 2;              // 0..63 row of A tile
    int ak = (tid & 3) << 2;        // 0,4,8,12 within k-tile
    int br = tid >> 4;              // 0..15 k-row of B tile
    int bc = (tid & 15) << 2;       // col within B tile

    for (int k0 = 0; k0 < ND; k0 += 16) {
        float4 av = *(const float4*)(X + (m0 + ar) * ND + k0 + ak);
        float4 bvv = *(const float4*)(W + (k0 + br) * ND + n0 + bc);
        __syncthreads();
        As[ak + 0][ar] = av.x;
        As[ak + 1][ar] = av.y;
        As[ak + 2][ar] = av.z;
        As[ak + 3][ar] = av.w;
        *(float4*)(&Bs[br][bc]) = bvv;
        __syncthreads();
        #pragma unroll
        for (int kk = 0; kk < 16; kk++) {
            float a[4], bb_[4];
            #pragma unroll
            for (int i = 0; i < 4; i++) a[i] = As[kk][ty * 4 + i];
            #pragma unroll
            for (int j = 0; j < 4; j++) bb_[j] = Bs[kk][tx * 4 + j];
            #pragma unroll
            for (int i = 0; i < 4; i++)
                #pragma unroll
                for (int j = 0; j < 4; j++)
                    acc[i][j] = fmaf(a[i], bb_[j], acc[i][j]);
        }
    }

    #pragma unroll
    for (int i = 0; i < 4; i++) {
        int row = m0 + ty * 4 + i;
        #pragma unroll
        for (int j = 0; j < 4; j++) {
            int col = n0 + tx * 4 + j;
            float yv = acc[i][j] + bias[col];
            Y[row * ND + col] = elu_f(yv);
        }
    }
}

// =====================================================================
// Kernel 2 (the monster): per (b,h,q,f-half=256f):
//   for all k: y[f] = relu(sum_d eqk[q,d]*ekk[k,d]*WKB[d,f] + bKB[f])
//   logit_part[k] = sum_f y[f]*Wb[f];  pool[f] += y[f]*mask[b,q,k]
// 128 threads: fg = tid>>3 (16 f-groups x 16f), kg = tid&7 (8 k-groups x 4k/chunk)
// 4 chunks of 32 k. Inner loop: pure LDS.128 + fma.rn.f32x2.
// =====================================================================
#define SM_W2    0                      // u64[64][128]  = 65536 B (WKB pairs, this half)
#define SM_A2    65536                  // u64[64][32]   = 16384 B ({a,a} pairs, d-major)
#define SM_EKK   (65536+16384)          // float[32][65] = 8320 B
#define SM_PART  (65536+16384+8320)     // float[32][16] = 2048 B
#define SM_POOLR (65536+16384+8320+2048)        // float[8][256] = 8192 B
#define SM_EQK   (65536+16384+8320+2048+8192)   // float[64] = 256 B
#define SMEM_BK  (65536+16384+8320+2048+8192+256)

__global__ __launch_bounds__(128, 2) void k_bk(
    const float* __restrict__ WKB, const float* __restrict__ bKB,
    const float* __restrict__ Wb,  const float* __restrict__ mask)
{
    extern __shared__ char smem[];
    unsigned long long* sW2 = (unsigned long long*)(smem + SM_W2);
    unsigned long long* sA2 = (unsigned long long*)(smem + SM_A2);
    float* sEkk   = (float*)(smem + SM_EKK);
    float* sPart  = (float*)(smem + SM_PART);
    float* sPoolR = (float*)(smem + SM_POOLR);
    float* seqk   = (float*)(smem + SM_EQK);

    int tid = threadIdx.x;
    int fg = tid >> 3;          // 0..15
    int kg = tid & 7;           // 0..7
    int bhq = blockIdx.x;       // 0..2047
    int fh  = blockIdx.y;       // 0..1
    int b  = bhq >> 10;
    int h  = (bhq >> 7) & 7;
    int qq = bhq & 127;
    int f0 = fh * 256;
    int hd0 = h * 64;
    int rowq = b * NS + qq;

    // Load WKB half into smem (pairs are naturally contiguous floats).
    for (int i = tid; i < 64 * 64; i += 128) {       // 4096 float4 = 16384 floats
        int d = i >> 6, c4 = (i & 63) << 2;
        float4 w = *(const float4*)(WKB + d * NFB + f0 + c4);
        *(float4*)((float*)(sW2 + (size_t)d * 128) + c4) = w;
    }
    if (tid < 64) seqk[tid] = g_eqk[rowq * ND + hd0 + tid];

    int fbase = f0 + fg * 16;
    float wb[16], pool[16];
    unsigned long long bkb2[8];
    #pragma unroll
    for (int j = 0; j < 16; j++) { wb[j] = Wb[fbase + j]; pool[j] = 0.f; }
    #pragma unroll
    for (int p = 0; p < 8; p++)
        bkb2[p] = pack2(bKB[fbase + 2 * p], bKB[fbase + 2 * p + 1]);

    unsigned long long acc[4][8];
    #pragma unroll
    for (int i = 0; i < 4; i++)
        #pragma unroll
        for (int p = 0; p < 8; p++) acc[i][p] = 0ULL;

    const float* ekk_base = g_ekk + (size_t)(b * NS) * ND + hd0;
    const float* mrow = mask + (size_t)rowq * NS;

    #pragma unroll 1
    for (int c = 0; c < 4; c++) {
        int k0 = c * 32;
        __syncthreads();   // prior readers of sA2/sEkk/sPart done; init loads visible (c==0)
        // stage ekk chunk, coalesced
        for (int i = tid; i < 32 * 64; i += 128) {
            int k = i >> 6, d = i & 63;
            sEkk[k * 65 + d] = ekk_base[(size_t)(k0 + k) * ND + d];
        }
        __syncthreads();
        // build duplicated {a,a} pairs, d-major (conflict-free both sides)
        for (int i = tid; i < 64 * 32; i += 128) {
            int d = i >> 5, k = i & 31;
            float a = seqk[d] * sEkk[k * 65 + d];
            sA2[d * 32 + k] = pack2(a, a);
        }
        __syncthreads();

        // ---- main loop: 64 d-steps, 32 FMA2 each ----
        const unsigned long long* wp = sW2 + fg * 8;
        const unsigned long long* ap = sA2 + kg * 4;
        #pragma unroll 4
        for (int d = 0; d < 64; d++) {
            ulonglong2 w0 = ((const ulonglong2*)wp)[0];
            ulonglong2 w1 = ((const ulonglong2*)wp)[1];
            ulonglong2 w2 = ((const ulonglong2*)wp)[2];
            ulonglong2 w3 = ((const ulonglong2*)wp)[3];
            ulonglong2 a0 = ((const ulonglong2*)ap)[0];
            ulonglong2 a1 = ((const ulonglong2*)ap)[1];
            unsigned long long av[4] = {a0.x, a0.y, a1.x, a1.y};
            unsigned long long wv[8] = {w0.x, w0.y, w1.x, w1.y, w2.x, w2.y, w3.x, w3.y};
            #pragma unroll
            for (int i = 0; i < 4; i++)
                #pragma unroll
                for (int p = 0; p < 8; p++)
                    fma2(acc[i][p], av[i], wv[p]);
            wp += 128;
            ap += 32;
        }

        // ---- chunk epilogue: bias + relu, reduce to logits/pool ----
        #pragma unroll
        for (int i = 0; i < 4; i++) {
            float mk = mrow[k0 + kg * 4 + i];
            float lgp = 0.f;
            #pragma unroll
            for (int p = 0; p < 8; p++) {
                unsigned long long t = add2(acc[i][p], bkb2[p]);
                float2 y = unpack2(t);
                y.x = fmaxf(y.x, 0.f);
                y.y = fmaxf(y.y, 0.f);
                lgp = fmaf(y.x, wb[2 * p], lgp);
                lgp = fmaf(y.y, wb[2 * p + 1], lgp);
                pool[2 * p]     = fmaf(y.x, mk, pool[2 * p]);
                pool[2 * p + 1] = fmaf(y.y, mk, pool[2 * p + 1]);
                acc[i][p] = 0ULL;
            }
            sPart[(kg * 4 + i) * 16 + fg] = lgp;
        }
        __syncthreads();
        if (tid < 32) {
            float s = 0.f;
            #pragma unroll
            for (int g = 0; g < 16; g++) s += sPart[tid * 16 + g];
            g_logit_part[(size_t)(fh * NBHQ + bhq) * NS + k0 + tid] = s;
        }
    }

    // ---- pool reduce over the 8 k-groups ----
    __syncthreads();
    #pragma unroll
    for (int j = 0; j < 16; j++) sPoolR[kg * 256 + fg * 16 + j] = pool[j];
    __syncthreads();
    for (int i = tid; i < 256; i += 128) {
        float s = 0.f;
        #pragma unroll
        for (int g = 0; g < 8; g++) s += sPoolR[g * 256 + i];
        g_pool[(size_t)bhq * NFB + f0 + i] = s;
    }
}

// =====================================================================
// Kernel 3: per (b,h,q): softmax over k, pool-avg -> channel (sigmoid),
// context = eqv * (attn @ evv), O = ctx * channel.
// =====================================================================
__global__ __launch_bounds__(128) void k_epi(
    const float* __restrict__ mask, const float* __restrict__ bbp,
    const float* __restrict__ We,   const float* __restrict__ be)
{
    __shared__ float sred[128];
    __shared__ float sattn[128];
    __shared__ float spav[512];

    int tid = threadIdx.x;
    int bhq = blockIdx.x;
    int b  = bhq >> 10;
    int h  = (bhq >> 7) & 7;
    int qq = bhq & 127;
    int hd0 = h * 64;
    int rowq = b * NS + qq;

    float mk = mask[(size_t)rowq * NS + tid];
    float lg = g_logit_part[(size_t)bhq * NS + tid]
             + g_logit_part[(size_t)(NBHQ + bhq) * NS + tid]
             + bbp[0] + (1.f - mk) * (-1e9f);

    // max-reduce
    sred[tid] = lg;
    __syncthreads();
    for (int s = 64; s > 0; s >>= 1) {
        if (tid < s) sred[tid] = fmaxf(sred[tid], sred[tid + s]);
        __syncthreads();
    }
    float m = sred[0];
    __syncthreads();
    float e = expf(lg - m);
    sred[tid] = e;
    __syncthreads();
    for (int s = 64; s > 0; s >>= 1) {
        if (tid < s) sred[tid] += sred[tid + s];
        __syncthreads();
    }
    float esum = sred[0];
    __syncthreads();
    sattn[tid] = e / esum;
    sred[tid] = mk;
    __syncthreads();
    for (int s = 64; s > 0; s >>= 1) {
        if (tid < s) sred[tid] += sred[tid + s];
        __syncthreads();
    }
    float msum = sred[0];
    __syncthreads();

    for (int f = tid; f < NFB; f += 128)
        spav[f] = g_pool[(size_t)bhq * NFB + f] / msum;
    __syncthreads();

    if (tid < 64) {
        int d = tid;
        float s = be[d];
        #pragma unroll 8
        for (int f = 0; f < NFB; f++) s = fmaf(spav[f], We[f * NKD + d], s);
        float ch = 1.f / (1.f + expf(-s));
        float cs = 0.f;
        const float* evvp = g_evv + (size_t)(b * NS) * ND + hd0 + d;
        #pragma unroll 8
        for (int k = 0; k < NS; k++) cs = fmaf(sattn[k], evvp[(size_t)k * ND], cs);
        g_O[(size_t)rowq * ND + hd0 + d] =
            g_eqv[(size_t)rowq * ND + hd0 + d] * cs * ch;
    }
}

// =====================================================================
// Kernel 4: out = O @ Wd + bd   (256x512)@(512x64)
// =====================================================================
__global__ __launch_bounds__(128) void k_final(
    const float* __restrict__ Wd, const float* __restrict__ bd,
    float* __restrict__ out)
{
    int tid = threadIdx.x;
    int r = blockIdx.x * 2 + (tid >> 6);
    int c = tid & 63;
    float s = bd[c];
    const float* orow = g_O + (size_t)r * ND;
    #pragma unroll 8
    for (int d = 0; d < ND; d++) s = fmaf(orow[d], Wd[d * NKD + c], s);
    out[(size_t)r * NKD + c] = s;
}

// =====================================================================
extern "C" void kernel_launch(void* const* d_in, const int* in_sizes, int n_in,
                              void* d_out, int out_size)
{
    const float* q    = (const float*)d_in[0];
    const float* v    = (const float*)d_in[1];
    const float* mask = (const float*)d_in[2];
    const float* Wkq  = (const float*)d_in[3];
    const float* bkq  = (const float*)d_in[4];
    const float* Wvq  = (const float*)d_in[5];
    const float* bvq  = (const float*)d_in[6];
    const float* Wk   = (const float*)d_in[7];
    const float* bk   = (const float*)d_in[8];
    const float* Wv   = (const float*)d_in[9];
    const float* bv   = (const float*)d_in[10];
    const float* WKB  = (const float*)d_in[11];
    const float* bKB  = (const float*)d_in[12];
    const float* Wb   = (const float*)d_in[13];
    const float* bb   = (const float*)d_in[14];
    const float* We   = (const float*)d_in[15];
    const float* be   = (const float*)d_in[16];
    const float* Wd   = (const float*)d_in[17];
    const float* bd   = (const float*)d_in[18];
    float* out = (float*)d_out;

    cudaFuncSetAttribute(k_bk, cudaFuncAttributeMaxDynamicSharedMemorySize, SMEM_BK);

    k_proj<<<dim3(8, 4, 4), 256>>>(q, v, Wkq, bkq, Wvq, bvq, Wk, bk, Wv, bv);
    k_bk<<<dim3(NBHQ, 2), 128, SMEM_BK>>>(WKB, bKB, Wb, mask);
    k_epi<<<NBHQ, 128>>>(mask, bb, We, be);
    k_final<<<128, 128>>>(Wd, bd, out);
}

// round 6
// speedup vs baseline: 1.7043x; 1.7043x over previous
#include <cuda_runtime.h>
#include <cuda_fp16.h>
#include <math.h>
#include <stdint.h>

// Shapes: B=2, S=128, H=8, KD=64, D=512, FB=512
#define NB   2
#define NS   128
#define NH   8
#define NKD  64
#define ND   512
#define NFB  512
#define NBHQ 2048

// ---------------- device scratch ----------------
__device__ float g_eqk[NB*NS*ND];
__device__ float g_eqv[NB*NS*ND];
__device__ float g_ekk[NB*NS*ND];
__device__ float g_evv[NB*NS*ND];
__device__ float g_logits[NBHQ*NS];
__device__ float g_pool[NBHQ*NFB];
__device__ float g_O[NB*NS*ND];

__device__ __forceinline__ float elu_f(float x) {
    return (x > 0.f) ? x : expm1f(x);
}

__device__ __forceinline__ uint32_t smem_to_u32(const void* smem_ptr) {
    uint32_t addr;
    asm("{ .reg .u64 tmp; cvta.to.shared.u64 tmp, %1; cvt.u32.u64 %0, tmp; }"
        : "=r"(addr) : "l"(smem_ptr));
    return addr;
}

#define LDSM4(r0, r1, r2, r3, addr) \
    asm volatile("ldmatrix.sync.aligned.m8n8.x4.shared.b16 {%0,%1,%2,%3}, [%4];" \
        : "=r"(r0), "=r"(r1), "=r"(r2), "=r"(r3) : "r"(addr))

#define MMA16816(c, a0, a1, a2, a3, b0, b1) \
    asm volatile("mma.sync.aligned.m16n8k16.row.col.f32.f16.f16.f32 " \
        "{%0,%1,%2,%3}, {%4,%5,%6,%7}, {%8,%9}, {%0,%1,%2,%3};" \
        : "+f"((c)[0]), "+f"((c)[1]), "+f"((c)[2]), "+f"((c)[3]) \
        : "r"(a0), "r"(a1), "r"(a2), "r"(a3), "r"(b0), "r"(b1))

// =====================================================================
// Kernel 1: four projections + elu
// =====================================================================
__global__ __launch_bounds__(256) void k_proj(
    const float* __restrict__ q, const float* __restrict__ v,
    const float* __restrict__ Wkq, const float* __restrict__ bkq,
    const float* __restrict__ Wvq, const float* __restrict__ bvq,
    const float* __restrict__ Wk,  const float* __restrict__ bk,
    const float* __restrict__ Wv,  const float* __restrict__ bv)
{
    int z = blockIdx.z;
    const float* X    = (z < 2) ? q : v;
    const float* W    = (z == 0) ? Wkq : (z == 1) ? Wvq : (z == 2) ? Wk : Wv;
    const float* bias = (z == 0) ? bkq : (z == 1) ? bvq : (z == 2) ? bk : bv;
    float* Y          = (z == 0) ? g_eqk : (z == 1) ? g_eqv : (z == 2) ? g_ekk : g_evv;

    __shared__ float As[16][64];
    __shared__ float Bs[16][64];

    int tid = threadIdx.x;
    int tx = tid & 15;
    int ty = tid >> 4;
    int n0 = blockIdx.x * 64;
    int m0 = blockIdx.y * 64;

    float acc[4][4];
    #pragma unroll
    for (int i = 0; i < 4; i++)
        #pragma unroll
        for (int j = 0; j < 4; j++) acc[i][j] = 0.f;

    int ar = tid >> 2;
    int ak = (tid & 3) << 2;
    int br = tid >> 4;
    int bc = (tid & 15) << 2;

    for (int k0 = 0; k0 < ND; k0 += 16) {
        float4 av = *(const float4*)(X + (m0 + ar) * ND + k0 + ak);
        float4 bvv = *(const float4*)(W + (k0 + br) * ND + n0 + bc);
        __syncthreads();
        As[ak + 0][ar] = av.x;
        As[ak + 1][ar] = av.y;
        As[ak + 2][ar] = av.z;
        As[ak + 3][ar] = av.w;
        *(float4*)(&Bs[br][bc]) = bvv;
        __syncthreads();
        #pragma unroll
        for (int kk = 0; kk < 16; kk++) {
            float a[4], bb_[4];
            #pragma unroll
            for (int i = 0; i < 4; i++) a[i] = As[kk][ty * 4 + i];
            #pragma unroll
            for (int j = 0; j < 4; j++) bb_[j] = Bs[kk][tx * 4 + j];
            #pragma unroll
            for (int i = 0; i < 4; i++)
                #pragma unroll
                for (int j = 0; j < 4; j++)
                    acc[i][j] = fmaf(a[i], bb_[j], acc[i][j]);
        }
    }

    #pragma unroll
    for (int i = 0; i < 4; i++) {
        int row = m0 + ty * 4 + i;
        #pragma unroll
        for (int j = 0; j < 4; j++) {
            int col = n0 + tx * 4 + j;
            Y[row * ND + col] = elu_f(acc[i][j] + bias[col]);
        }
    }
}

// =====================================================================
// Kernel 2 (monster, mma.sync fp16x3): persistent 128 blocks x 16 tiles.
// Per tile (b,h,q): D[128k,512f] = A @ W with A,W split hp16 hi/lo:
//   D = Ahi@Whi + Alo@Whi + Ahi@Wlo   (lo@lo dropped, ~2^-22)
// Epilogue fused in registers: y=relu(D+bKB); logits[k]=y@Wb; pool[f]=sum_k y*mk.
// 256 threads = 8 warps; warp w owns k rows [16w, 16w+16).
// smem rows are 128B with XOR-16B swizzle: chunk' = chunk ^ (row&7).
// =====================================================================
#define SW_WT_HI 0                    // half [512 f][64 d]  = 65536
#define SW_WT_LO 65536                // 65536
#define SW_A_HI  131072               // half [128 k][64 d]  = 16384
#define SW_A_LO  147456               // 16384
#define SW_EKK   163840               // float [128][65]     = 33280
#define SW_EQK   197120               // float [64]          = 256
#define SW_MASK  197376               // float [128]         = 512
#define SW_WB    197888               // float [512]         = 2048
#define SW_BKB   199936               // float [512]         = 2048
#define SW_POOLW 201984               // float [8][128]      = 4096
#define SMEM_MMA 206080

__global__ __launch_bounds__(256, 1) void k_bk_mma(
    const float* __restrict__ WKB, const float* __restrict__ bKB,
    const float* __restrict__ Wb,  const float* __restrict__ mask)
{
    extern __shared__ char smem[];
    uint32_t sb = smem_to_u32(smem);
    float* sEkk  = (float*)(smem + SW_EKK);
    float* sEqk  = (float*)(smem + SW_EQK);
    float* sMask = (float*)(smem + SW_MASK);
    float* sWb   = (float*)(smem + SW_WB);
    float* sBKB  = (float*)(smem + SW_BKB);
    float* sPoolW = (float*)(smem + SW_POOLW);

    int tid = threadIdx.x;
    int w = tid >> 5, lane = tid & 31;
    int g = lane >> 2, tig = lane & 3;
    int t0 = blockIdx.x * 16;
    int b = t0 >> 10, h = (t0 >> 7) & 7;
    int hd0 = h * NKD;

    // ---- stage W hi/lo into swizzled smem (once per block) ----
    for (int i = tid; i < NFB * 32; i += 256) {
        int f = i & 511;
        int dp = (i >> 9) * 2;                     // even d
        float w0 = WKB[dp * NFB + f];
        float w1 = WKB[(dp + 1) * NFB + f];
        __half h0 = __float2half_rn(w0);
        __half h1 = __float2half_rn(w1);
        __half l0 = __float2half_rn(w0 - __half2float(h0));
        __half l1 = __float2half_rn(w1 - __half2float(h1));
        uint32_t off = (uint32_t)(f * 128 + (((dp >> 3) ^ (f & 7)) << 4) + (dp & 7) * 2);
        *(__half2*)(smem + SW_WT_HI + off) = __halves2half2(h0, h1);
        *(__half2*)(smem + SW_WT_LO + off) = __halves2half2(l0, l1);
    }
    // ---- ekk (constant per block) ----
    const float* ekk_base = g_ekk + (size_t)(b * NS) * ND + hd0;
    for (int i = tid; i < NS * NKD; i += 256) {
        int k = i >> 6, d = i & 63;
        sEkk[k * 65 + d] = ekk_base[(size_t)k * ND + d];
    }
    for (int i = tid; i < NFB; i += 256) { sWb[i] = Wb[i]; sBKB[i] = bKB[i]; }
    __syncthreads();

    int arow = w * 16 + (lane & 7) + (lane & 8);
    int dhalf = lane >> 4;

    for (int it = 0; it < 16; it++) {
        int t = t0 + it;
        int qq = t & 127;
        int rowq = b * NS + qq;

        if (tid < 64) sEqk[tid] = g_eqk[(size_t)rowq * ND + hd0 + tid];
        else if (tid >= 128) sMask[tid - 128] = mask[(size_t)rowq * NS + tid - 128];
        __syncthreads();

        // ---- build A hi/lo: thread handles (k = tid>>1, 32 d) ----
        {
            int k = tid >> 1;
            int dh = (tid & 1) * 32;
            const float* eq = sEqk + dh;
            const float* er = sEkk + k * 65 + dh;
            uint32_t rowoff = (uint32_t)(k * 128);
            int klow = k & 7;
            #pragma unroll
            for (int j = 0; j < 16; j++) {
                int d = dh + 2 * j;
                float a0 = eq[2 * j] * er[2 * j];
                float a1 = eq[2 * j + 1] * er[2 * j + 1];
                __half h0 = __float2half_rn(a0);
                __half h1 = __float2half_rn(a1);
                __half l0 = __float2half_rn(a0 - __half2float(h0));
                __half l1 = __float2half_rn(a1 - __half2float(h1));
                uint32_t off = rowoff + (uint32_t)((((d >> 3) ^ klow) << 4) + (d & 7) * 2);
                *(__half2*)(smem + SW_A_HI + off) = __halves2half2(h0, h1);
                *(__half2*)(smem + SW_A_LO + off) = __halves2half2(l0, l1);
            }
        }
        __syncthreads();

        float llog0 = 0.f, llog1 = 0.f;
        int kr0 = w * 16 + g, kr1 = kr0 + 8;
        float mk0 = sMask[kr0], mk1 = sMask[kr1];

        #pragma unroll 1
        for (int cf = 0; cf < 4; cf++) {
            float acc[16][4];
            #pragma unroll
            for (int nt = 0; nt < 16; nt++)
                #pragma unroll
                for (int c = 0; c < 4; c++) acc[nt][c] = 0.f;

            #pragma unroll
            for (int ks = 0; ks < 4; ks++) {
                int chnk = ks * 2 + dhalf;
                uint32_t aoff = (uint32_t)(arow * 128 + ((chnk ^ (arow & 7)) << 4));
                uint32_t ah0, ah1, ah2, ah3, al0, al1, al2, al3;
                LDSM4(ah0, ah1, ah2, ah3, sb + SW_A_HI + aoff);
                LDSM4(al0, al1, al2, al3, sb + SW_A_LO + aoff);
                #pragma unroll
                for (int ntp = 0; ntp < 8; ntp++) {
                    int frow = cf * 128 + ntp * 16 + (lane & 7) + (lane & 8);
                    uint32_t boff = (uint32_t)(frow * 128 + ((chnk ^ (frow & 7)) << 4));
                    uint32_t bh0, bh1, bh2, bh3, bl0, bl1, bl2, bl3;
                    LDSM4(bh0, bh1, bh2, bh3, sb + SW_WT_HI + boff);
                    LDSM4(bl0, bl1, bl2, bl3, sb + SW_WT_LO + boff);
                    MMA16816(acc[2 * ntp],     ah0, ah1, ah2, ah3, bh0, bh2);
                    MMA16816(acc[2 * ntp + 1], ah0, ah1, ah2, ah3, bh1, bh3);
                    MMA16816(acc[2 * ntp],     al0, al1, al2, al3, bh0, bh2);
                    MMA16816(acc[2 * ntp + 1], al0, al1, al2, al3, bh1, bh3);
                    MMA16816(acc[2 * ntp],     ah0, ah1, ah2, ah3, bl0, bl2);
                    MMA16816(acc[2 * ntp + 1], ah0, ah1, ah2, ah3, bl1, bl3);
                }
            }

            // ---- chunk epilogue ----
            int fb = cf * 128;
            #pragma unroll
            for (int nt = 0; nt < 16; nt++) {
                int f = fb + nt * 8 + 2 * tig;
                float bk0 = sBKB[f], bk1 = sBKB[f + 1];
                float y00 = fmaxf(acc[nt][0] + bk0, 0.f);
                float y01 = fmaxf(acc[nt][1] + bk1, 0.f);
                float y10 = fmaxf(acc[nt][2] + bk0, 0.f);
                float y11 = fmaxf(acc[nt][3] + bk1, 0.f);
                llog0 += y00 * sWb[f] + y01 * sWb[f + 1];
                llog1 += y10 * sWb[f] + y11 * sWb[f + 1];
                float p0 = y00 * mk0 + y10 * mk1;
                float p1 = y01 * mk0 + y11 * mk1;
                p0 += __shfl_xor_sync(0xffffffffu, p0, 4);
                p0 += __shfl_xor_sync(0xffffffffu, p0, 8);
                p0 += __shfl_xor_sync(0xffffffffu, p0, 16);
                p1 += __shfl_xor_sync(0xffffffffu, p1, 4);
                p1 += __shfl_xor_sync(0xffffffffu, p1, 8);
                p1 += __shfl_xor_sync(0xffffffffu, p1, 16);
                if (lane < 4) {
                    sPoolW[w * 128 + nt * 8 + 2 * lane]     = p0;
                    sPoolW[w * 128 + nt * 8 + 2 * lane + 1] = p1;
                }
            }
            __syncthreads();
            if (tid < 128) {
                float s = 0.f;
                #pragma unroll
                for (int ww = 0; ww < 8; ww++) s += sPoolW[ww * 128 + tid];
                g_pool[(size_t)t * NFB + fb + tid] = s;
            }
            __syncthreads();
        }

        // ---- logits: reduce over tig quad ----
        llog0 += __shfl_xor_sync(0xffffffffu, llog0, 1);
        llog0 += __shfl_xor_sync(0xffffffffu, llog0, 2);
        llog1 += __shfl_xor_sync(0xffffffffu, llog1, 1);
        llog1 += __shfl_xor_sync(0xffffffffu, llog1, 2);
        if (tig == 0) {
            g_logits[(size_t)t * NS + kr0] = llog0;
            g_logits[(size_t)t * NS + kr1] = llog1;
        }
        __syncthreads();   // all done with sEqk/sMask/A before next tile rewrites
    }
}

// =====================================================================
// Kernel 3: softmax + pool-avg -> channel sigmoid + ctx
// =====================================================================
__global__ __launch_bounds__(128) void k_epi(
    const float* __restrict__ mask, const float* __restrict__ bbp,
    const float* __restrict__ We,   const float* __restrict__ be)
{
    __shared__ float sred[128];
    __shared__ float sattn[128];
    __shared__ float spav[512];
    __shared__ float sc1[128];
    __shared__ float sc2[128];

    int tid = threadIdx.x;
    int bhq = blockIdx.x;
    int b = bhq >> 10, h = (bhq >> 7) & 7, qq = bhq & 127;
    int hd0 = h * NKD;
    int rowq = b * NS + qq;

    float mk = mask[(size_t)rowq * NS + tid];
    float lg = g_logits[(size_t)bhq * NS + tid] + bbp[0] + (1.f - mk) * (-1e9f);

    sred[tid] = lg; __syncthreads();
    for (int s = 64; s > 0; s >>= 1) {
        if (tid < s) sred[tid] = fmaxf(sred[tid], sred[tid + s]);
        __syncthreads();
    }
    float m = sred[0]; __syncthreads();
    float e = expf(lg - m);
    sred[tid] = e; __syncthreads();
    for (int s = 64; s > 0; s >>= 1) {
        if (tid < s) sred[tid] += sred[tid + s];
        __syncthreads();
    }
    float esum = sred[0]; __syncthreads();
    sattn[tid] = e / esum;
    sred[tid] = mk; __syncthreads();
    for (int s = 64; s > 0; s >>= 1) {
        if (tid < s) sred[tid] += sred[tid + s];
        __syncthreads();
    }
    float msum = sred[0]; __syncthreads();

    for (int f = tid; f < NFB; f += 128)
        spav[f] = g_pool[(size_t)bhq * NFB + f] / msum;
    __syncthreads();

    int d = tid & 63, hf = tid >> 6;
    {
        float a0 = 0, a1 = 0, a2 = 0, a3 = 0;
        const float* Wep = We + d;
        int fb = hf * 256;
        #pragma unroll 4
        for (int f = fb; f < fb + 256; f += 4) {
            a0 = fmaf(spav[f],     Wep[(size_t)f * NKD],       a0);
            a1 = fmaf(spav[f + 1], Wep[(size_t)(f + 1) * NKD], a1);
            a2 = fmaf(spav[f + 2], Wep[(size_t)(f + 2) * NKD], a2);
            a3 = fmaf(spav[f + 3], Wep[(size_t)(f + 3) * NKD], a3);
        }
        sc1[tid] = (a0 + a1) + (a2 + a3);
    }
    {
        float c0 = 0, c1 = 0, c2 = 0, c3 = 0;
        const float* evvp = g_evv + (size_t)(b * NS) * ND + hd0 + d;
        int kb = hf * 64;
        #pragma unroll 4
        for (int k = kb; k < kb + 64; k += 4) {
            c0 = fmaf(sattn[k],     evvp[(size_t)k * ND],       c0);
            c1 = fmaf(sattn[k + 1], evvp[(size_t)(k + 1) * ND], c1);
            c2 = fmaf(sattn[k + 2], evvp[(size_t)(k + 2) * ND], c2);
            c3 = fmaf(sattn[k + 3], evvp[(size_t)(k + 3) * ND], c3);
        }
        sc2[tid] = (c0 + c1) + (c2 + c3);
    }
    __syncthreads();
    if (tid < 64) {
        float ch = 1.f / (1.f + expf(-(sc1[tid] + sc1[tid + 64] + be[tid])));
        float cs = sc2[tid] + sc2[tid + 64];
        g_O[(size_t)rowq * ND + hd0 + tid] =
            g_eqv[(size_t)rowq * ND + hd0 + tid] * cs * ch;
    }
}

// =====================================================================
// Kernel 4: out = O @ Wd + bd  (256x512)@(512x64)
// =====================================================================
__global__ __launch_bounds__(128) void k_final(
    const float* __restrict__ Wd, const float* __restrict__ bd,
    float* __restrict__ out)
{
    __shared__ float sc[128];
    int tid = threadIdx.x;
    int r = blockIdx.x;
    int c = tid & 63, hf = tid >> 6;
    const float* orow = g_O + (size_t)r * ND + hf * 256;
    const float* wp = Wd + (size_t)(hf * 256) * NKD + c;
    float a0 = 0, a1 = 0, a2 = 0, a3 = 0;
    #pragma unroll 8
    for (int dd = 0; dd < 256; dd += 4) {
        a0 = fmaf(orow[dd],     wp[(size_t)dd * NKD],       a0);
        a1 = fmaf(orow[dd + 1], wp[(size_t)(dd + 1) * NKD], a1);
        a2 = fmaf(orow[dd + 2], wp[(size_t)(dd + 2) * NKD], a2);
        a3 = fmaf(orow[dd + 3], wp[(size_t)(dd + 3) * NKD], a3);
    }
    sc[tid] = (a0 + a1) + (a2 + a3);
    __syncthreads();
    if (tid < 64)
        out[(size_t)r * NKD + tid] = sc[tid] + sc[tid + 64] + bd[tid];
}

// =====================================================================
extern "C" void kernel_launch(void* const* d_in, const int* in_sizes, int n_in,
                              void* d_out, int out_size)
{
    const float* q    = (const float*)d_in[0];
    const float* v    = (const float*)d_in[1];
    const float* mask = (const float*)d_in[2];
    const float* Wkq  = (const float*)d_in[3];
    const float* bkq  = (const float*)d_in[4];
    const float* Wvq  = (const float*)d_in[5];
    const float* bvq  = (const float*)d_in[6];
    const float* Wk   = (const float*)d_in[7];
    const float* bk   = (const float*)d_in[8];
    const float* Wv   = (const float*)d_in[9];
    const float* bv   = (const float*)d_in[10];
    const float* WKB  = (const float*)d_in[11];
    const float* bKB  = (const float*)d_in[12];
    const float* Wb   = (const float*)d_in[13];
    const float* bb   = (const float*)d_in[14];
    const float* We   = (const float*)d_in[15];
    const float* be   = (const float*)d_in[16];
    const float* Wd   = (const float*)d_in[17];
    const float* bd   = (const float*)d_in[18];
    float* out = (float*)d_out;

    cudaFuncSetAttribute(k_bk_mma, cudaFuncAttributeMaxDynamicSharedMemorySize, SMEM_MMA);

    k_proj<<<dim3(8, 4, 4), 256>>>(q, v, Wkq, bkq, Wvq, bvq, Wk, bk, Wv, bv);
    k_bk_mma<<<128, 256, SMEM_MMA>>>(WKB, bKB, Wb, mask);
    k_epi<<<NBHQ, 128>>>(mask, bb, We, be);
    k_final<<<256, 128>>>(Wd, bd, out);
}